// round 1
// baseline (speedup 1.0000x reference)
#include <cuda_runtime.h>
#include <math.h>

#define BB 2
#define SS 4096
#define DD 128
#define HALF 64
#define TQ 32
#define KROWS (TQ + 2*HALF)   /* 160 */
#define QST 36                /* transposed-q row stride */
#define SCW 144               /* score row width, col offset +4, zero padded */
#define NEG_INF_F (-1e30f)

__device__ float g_q[BB*SS*DD];
__device__ float g_k[BB*SS*DD];
__device__ float g_v[BB*SS*DD];

// swizzled float index of 4-float chunk (r, d4) in a [rows][128] tile
__device__ __forceinline__ int swz(int r, int d4) {
    return r * DD + (((d4 ^ r) & 31) << 2);
}

#define QKV_FMA(A, XV, WV) \
    A.x = fmaf(XV, WV.x, A.x); A.y = fmaf(XV, WV.y, A.y); \
    A.z = fmaf(XV, WV.z, A.z); A.w = fmaf(XV, WV.w, A.w);

__global__ void __launch_bounds__(256) qkv_kernel(
    const float* __restrict__ x,
    const float* __restrict__ Wq, const float* __restrict__ bq,
    const float* __restrict__ Wk, const float* __restrict__ bk,
    const float* __restrict__ Wv, const float* __restrict__ bv)
{
    __shared__ float xs[32 * DD];
    const int tid  = threadIdx.x;
    const int row0 = blockIdx.x * 32;

    {   // load 32 x 128 x-tile (float4, coalesced)
        const float4* src = (const float4*)(x + (size_t)row0 * DD);
        float4* dst = (float4*)xs;
        for (int i = tid; i < 32 * DD / 4; i += 256) dst[i] = src[i];
    }
    __syncthreads();

    const int c4 = (tid & 31) << 2;   // output column base (4 cols)
    const int rg = tid >> 5;          // row group 0..7 -> rows rg, rg+8, rg+16, rg+24

    const float* W[3]    = {Wq, Wk, Wv};
    const float* bias[3] = {bq, bk, bv};
    float*       out[3]  = {g_q, g_k, g_v};

    for (int w = 0; w < 3; ++w) {
        float4 b4 = *(const float4*)(bias[w] + c4);
        float4 a0 = b4, a1 = b4, a2 = b4, a3 = b4;
        const float* Wp = W[w] + c4;
        #pragma unroll 4
        for (int k = 0; k < DD; ++k) {
            float4 wv = *(const float4*)(Wp + k * DD);   // L1/L2 resident
            float x0 = xs[(rg     ) * DD + k];           // broadcast LDS
            float x1 = xs[(rg +  8) * DD + k];
            float x2 = xs[(rg + 16) * DD + k];
            float x3 = xs[(rg + 24) * DD + k];
            QKV_FMA(a0, x0, wv);
            QKV_FMA(a1, x1, wv);
            QKV_FMA(a2, x2, wv);
            QKV_FMA(a3, x3, wv);
        }
        float* op = out[w] + (size_t)row0 * DD + c4;
        *(float4*)(op + (size_t)(rg     ) * DD) = a0;
        *(float4*)(op + (size_t)(rg +  8) * DD) = a1;
        *(float4*)(op + (size_t)(rg + 16) * DD) = a2;
        *(float4*)(op + (size_t)(rg + 24) * DD) = a3;
    }
}

// scores dot: q0..q3 are q[d..d+3][i0..i0+3] (components = i), kv = k[r][d..d+3]
#define DOT4(A, C, KV) \
    A = fmaf(q0.C, KV.x, A); A = fmaf(q1.C, KV.y, A); \
    A = fmaf(q2.C, KV.z, A); A = fmaf(q3.C, KV.w, A);

#define OUT_FMA(A, P, VV) \
    A.x = fmaf(P, VV.x, A.x); A.y = fmaf(P, VV.y, A.y); \
    A.z = fmaf(P, VV.z, A.z); A.w = fmaf(P, VV.w, A.w);

__global__ void __launch_bounds__(256, 1) attn_kernel(float* __restrict__ outp)
{
    extern __shared__ float sm[];
    float* ks   = sm;                    // [KROWS][128] swizzled
    float* vs   = ks  + KROWS * DD;      // [KROWS][128] swizzled
    float* qsT  = vs  + KROWS * DD;      // [128][QST]  q transposed
    float* sc   = qsT + DD * QST;        // [TQ][SCW]   col offset +4
    float* ssum = sc  + TQ * SCW;        // [TQ]

    const int tid = threadIdx.x;
    const int blk = blockIdx.x;
    const int b   = blk >> 7;            // / (SS/TQ)
    const int s0  = (blk & 127) * TQ;
    const int lo  = s0 - HALF;

    const float* kg = g_k + (size_t)b * SS * DD;
    const float* vg = g_v + (size_t)b * SS * DD;
    const float* qg = g_q + (size_t)b * SS * DD;

    // ---- load k/v window (zero-fill out-of-range rows), swizzled ----
    for (int idx = tid; idx < KROWS * 32; idx += 256) {
        int r = idx >> 5, d4 = idx & 31;
        int g = lo + r;
        float4 kv = make_float4(0.f, 0.f, 0.f, 0.f);
        float4 vv = make_float4(0.f, 0.f, 0.f, 0.f);
        if ((unsigned)g < SS) {
            kv = *(const float4*)(kg + (size_t)g * DD + (d4 << 2));
            vv = *(const float4*)(vg + (size_t)g * DD + (d4 << 2));
        }
        *(float4*)(ks + swz(r, d4)) = kv;
        *(float4*)(vs + swz(r, d4)) = vv;
    }
    // ---- load q transposed: qsT[d][i] ----
    for (int idx = tid; idx < TQ * DD; idx += 256) {
        int i = idx >> 7, d = idx & 127;
        qsT[d * QST + i] = qg[(size_t)(s0 + i) * DD + d];
    }
    // ---- zero score array (padding cols must stay 0) ----
    for (int idx = tid; idx < TQ * SCW; idx += 256) sc[idx] = 0.f;
    __syncthreads();

    // ---- scores: 264 band tiles of 4 queries x 4 key-rows ----
    const float scale = 0.08838834764831844f;  // 1/sqrt(128)
    for (int t = tid; t < 264; t += 256) {
        int it = t & 7, rt = t >> 3;
        int i0 = it << 2;
        int r0 = i0 + (rt << 2);     // key rows r0..r0+3, covers j = r - i in [0,128]
        float a00=0,a01=0,a02=0,a03=0, a10=0,a11=0,a12=0,a13=0;
        float a20=0,a21=0,a22=0,a23=0, a30=0,a31=0,a32=0,a33=0;
        #pragma unroll 2
        for (int d = 0; d < DD; d += 4) {
            float4 q0 = *(float4*)(qsT + (d + 0) * QST + i0);
            float4 q1 = *(float4*)(qsT + (d + 1) * QST + i0);
            float4 q2 = *(float4*)(qsT + (d + 2) * QST + i0);
            float4 q3 = *(float4*)(qsT + (d + 3) * QST + i0);
            int d4 = d >> 2;
            float4 k0 = *(float4*)(ks + swz(r0 + 0, d4));
            float4 k1 = *(float4*)(ks + swz(r0 + 1, d4));
            float4 k2 = *(float4*)(ks + swz(r0 + 2, d4));
            float4 k3 = *(float4*)(ks + swz(r0 + 3, d4));
            DOT4(a00, x, k0); DOT4(a01, x, k1); DOT4(a02, x, k2); DOT4(a03, x, k3);
            DOT4(a10, y, k0); DOT4(a11, y, k1); DOT4(a12, y, k2); DOT4(a13, y, k3);
            DOT4(a20, z, k0); DOT4(a21, z, k1); DOT4(a22, z, k2); DOT4(a23, z, k3);
            DOT4(a30, w, k0); DOT4(a31, w, k1); DOT4(a32, w, k2); DOT4(a33, w, k3);
        }
        float accs[4][4] = {{a00,a01,a02,a03},{a10,a11,a12,a13},
                            {a20,a21,a22,a23},{a30,a31,a32,a33}};
        #pragma unroll
        for (int w = 0; w < 4; ++w) {
            int r = r0 + w;
            bool kvalid = ((unsigned)(lo + r) < SS);
            #pragma unroll
            for (int u = 0; u < 4; ++u) {
                int i = i0 + u;
                int j = r - i;
                if (j >= 0 && j <= 128)
                    sc[i * SCW + 4 + j] = kvalid ? accs[u][w] * scale : NEG_INF_F;
            }
        }
    }
    __syncthreads();

    // ---- softmax per row: 8 lanes per row, sub-warp shfl reductions ----
    {
        int i = tid >> 3, jb = tid & 7;
        float* row = sc + i * SCW + 4;
        float m = -INFINITY;
        #pragma unroll
        for (int t = 0; t < 17; ++t) {
            int j = jb + (t << 3);
            if (j < 129) m = fmaxf(m, row[j]);
        }
        m = fmaxf(m, __shfl_xor_sync(0xffffffffu, m, 1, 8));
        m = fmaxf(m, __shfl_xor_sync(0xffffffffu, m, 2, 8));
        m = fmaxf(m, __shfl_xor_sync(0xffffffffu, m, 4, 8));
        float sum = 0.f;
        #pragma unroll
        for (int t = 0; t < 17; ++t) {
            int j = jb + (t << 3);
            if (j < 129) {
                float e = __expf(row[j] - m);
                row[j] = e;
                sum += e;
            }
        }
        sum += __shfl_xor_sync(0xffffffffu, sum, 1, 8);
        sum += __shfl_xor_sync(0xffffffffu, sum, 2, 8);
        sum += __shfl_xor_sync(0xffffffffu, sum, 4, 8);
        if (jb == 0) ssum[i] = sum;
    }
    __syncthreads();

    // ---- output: 4 queries x 4 dims per thread over the 132-row band ----
    {
        int it = tid >> 5, dt = tid & 31;
        int i0 = it << 2;
        float4 o0 = make_float4(0,0,0,0), o1 = o0, o2 = o0, o3 = o0;
        #pragma unroll 4
        for (int rr = 0; rr < 132; ++rr) {
            int r = i0 + rr;
            float4 vv = *(float4*)(vs + swz(r, dt));
            const float* srow = sc + i0 * SCW + 4 + (r - i0);
            float p0 = srow[0];              // j = r - i0       (zero-padded OOB)
            float p1 = srow[SCW - 1];        // j = r - (i0+1)
            float p2 = srow[2 * SCW - 2];
            float p3 = srow[3 * SCW - 3];
            OUT_FMA(o0, p0, vv);
            OUT_FMA(o1, p1, vv);
            OUT_FMA(o2, p2, vv);
            OUT_FMA(o3, p3, vv);
        }
        float inv0 = 1.0f / ssum[i0 + 0];
        float inv1 = 1.0f / ssum[i0 + 1];
        float inv2 = 1.0f / ssum[i0 + 2];
        float inv3 = 1.0f / ssum[i0 + 3];
        float* op = outp + ((size_t)b * SS + s0 + i0) * DD + (dt << 2);
        *(float4*)(op + 0 * DD) = make_float4(o0.x*inv0, o0.y*inv0, o0.z*inv0, o0.w*inv0);
        *(float4*)(op + 1 * DD) = make_float4(o1.x*inv1, o1.y*inv1, o1.z*inv1, o1.w*inv1);
        *(float4*)(op + 2 * DD) = make_float4(o2.x*inv2, o2.y*inv2, o2.z*inv2, o2.w*inv2);
        *(float4*)(op + 3 * DD) = make_float4(o3.x*inv3, o3.y*inv3, o3.z*inv3, o3.w*inv3);
    }
}

extern "C" void kernel_launch(void* const* d_in, const int* in_sizes, int n_in,
                              void* d_out, int out_size)
{
    const float* x  = (const float*)d_in[0];
    const float* Wq = (const float*)d_in[1];
    const float* bq = (const float*)d_in[2];
    const float* Wk = (const float*)d_in[3];
    const float* bk = (const float*)d_in[4];
    const float* Wv = (const float*)d_in[5];
    const float* bv = (const float*)d_in[6];
    float* out = (float*)d_out;

    const int smem_bytes = (2 * KROWS * DD + DD * QST + TQ * SCW + TQ) * (int)sizeof(float);
    cudaFuncSetAttribute(attn_kernel, cudaFuncAttributeMaxDynamicSharedMemorySize, smem_bytes);

    qkv_kernel<<<BB * SS / 32, 256>>>(x, Wq, bq, Wk, bk, Wv, bv);
    attn_kernel<<<BB * SS / TQ, 256, smem_bytes>>>(out);
}

// round 2
// speedup vs baseline: 1.1335x; 1.1335x over previous
#include <cuda_runtime.h>
#include <math.h>

#define BB 2
#define SS 4096
#define DD 128
#define HALF 64
#define TQ 32
#define KROWS (TQ + 2*HALF)   /* 160 */
#define QST 36                /* transposed-q row stride */
#define SCW 136               /* score row width: 4 front pad + 129 + 3 back pad */
#define NEG_INF_F (-1e30f)

__device__ float g_q[BB*SS*DD];
__device__ float g_k[BB*SS*DD];
__device__ float g_v[BB*SS*DD];

// swizzled float index of 4-float chunk (r, d4) in a [rows][128] tile
__device__ __forceinline__ int swz(int r, int d4) {
    return r * DD + (((d4 ^ r) & 31) << 2);
}

#define QKV_FMA(A, XV, WV) \
    A.x = fmaf(XV, WV.x, A.x); A.y = fmaf(XV, WV.y, A.y); \
    A.z = fmaf(XV, WV.z, A.z); A.w = fmaf(XV, WV.w, A.w);

__global__ void __launch_bounds__(256) qkv_kernel(
    const float* __restrict__ x,
    const float* __restrict__ Wq, const float* __restrict__ bq,
    const float* __restrict__ Wk, const float* __restrict__ bk,
    const float* __restrict__ Wv, const float* __restrict__ bv)
{
    __shared__ float xs[32 * DD];
    const int tid  = threadIdx.x;
    const int row0 = blockIdx.x * 32;

    {   // load 32 x 128 x-tile (float4, coalesced)
        const float4* src = (const float4*)(x + (size_t)row0 * DD);
        float4* dst = (float4*)xs;
        for (int i = tid; i < 32 * DD / 4; i += 256) dst[i] = src[i];
    }
    __syncthreads();

    const int c4 = (tid & 31) << 2;   // output column base (4 cols)
    const int rg = tid >> 5;          // row group 0..7 -> rows rg, rg+8, rg+16, rg+24

    const float* W[3]    = {Wq, Wk, Wv};
    const float* bias[3] = {bq, bk, bv};
    float*       out[3]  = {g_q, g_k, g_v};

    for (int w = 0; w < 3; ++w) {
        float4 b4 = *(const float4*)(bias[w] + c4);
        float4 a0 = b4, a1 = b4, a2 = b4, a3 = b4;
        const float* Wp = W[w] + c4;
        #pragma unroll 4
        for (int k = 0; k < DD; ++k) {
            float4 wv = *(const float4*)(Wp + k * DD);   // L1/L2 resident
            float x0 = xs[(rg     ) * DD + k];           // broadcast LDS
            float x1 = xs[(rg +  8) * DD + k];
            float x2 = xs[(rg + 16) * DD + k];
            float x3 = xs[(rg + 24) * DD + k];
            QKV_FMA(a0, x0, wv);
            QKV_FMA(a1, x1, wv);
            QKV_FMA(a2, x2, wv);
            QKV_FMA(a3, x3, wv);
        }
        float* op = out[w] + (size_t)row0 * DD + c4;
        *(float4*)(op + (size_t)(rg     ) * DD) = a0;
        *(float4*)(op + (size_t)(rg +  8) * DD) = a1;
        *(float4*)(op + (size_t)(rg + 16) * DD) = a2;
        *(float4*)(op + (size_t)(rg + 24) * DD) = a3;
    }
}

// scores dot: q0..q3 are q[d..d+3][i0..i0+3] (components = i), KV = k[r][d..d+3]
#define DOT4(A, C, KV) \
    A = fmaf(q0.C, KV.x, A); A = fmaf(q1.C, KV.y, A); \
    A = fmaf(q2.C, KV.z, A); A = fmaf(q3.C, KV.w, A);

#define OUT_FMA(A, P, VV) \
    A.x = fmaf(P, VV.x, A.x); A.y = fmaf(P, VV.y, A.y); \
    A.z = fmaf(P, VV.z, A.z); A.w = fmaf(P, VV.w, A.w);

// compute 4 queries x 4 key-rows score tile into out[u*4+w] (u=query, w=keyrow)
__device__ __forceinline__ void score_tile(
    const float* __restrict__ qsT, const float* __restrict__ ks,
    int i0, int r0, float* __restrict__ out)
{
    float a00=0,a01=0,a02=0,a03=0, a10=0,a11=0,a12=0,a13=0;
    float a20=0,a21=0,a22=0,a23=0, a30=0,a31=0,a32=0,a33=0;
    #pragma unroll 2
    for (int d = 0; d < DD; d += 4) {
        float4 q0 = *(const float4*)(qsT + (d + 0) * QST + i0);
        float4 q1 = *(const float4*)(qsT + (d + 1) * QST + i0);
        float4 q2 = *(const float4*)(qsT + (d + 2) * QST + i0);
        float4 q3 = *(const float4*)(qsT + (d + 3) * QST + i0);
        int d4 = d >> 2;
        float4 k0 = *(const float4*)(ks + swz(r0 + 0, d4));
        float4 k1 = *(const float4*)(ks + swz(r0 + 1, d4));
        float4 k2 = *(const float4*)(ks + swz(r0 + 2, d4));
        float4 k3 = *(const float4*)(ks + swz(r0 + 3, d4));
        DOT4(a00, x, k0); DOT4(a01, x, k1); DOT4(a02, x, k2); DOT4(a03, x, k3);
        DOT4(a10, y, k0); DOT4(a11, y, k1); DOT4(a12, y, k2); DOT4(a13, y, k3);
        DOT4(a20, z, k0); DOT4(a21, z, k1); DOT4(a22, z, k2); DOT4(a23, z, k3);
        DOT4(a30, w, k0); DOT4(a31, w, k1); DOT4(a32, w, k2); DOT4(a33, w, k3);
    }
    out[0]=a00;  out[1]=a01;  out[2]=a02;  out[3]=a03;
    out[4]=a10;  out[5]=a11;  out[6]=a12;  out[7]=a13;
    out[8]=a20;  out[9]=a21;  out[10]=a22; out[11]=a23;
    out[12]=a30; out[13]=a31; out[14]=a32; out[15]=a33;
}

__global__ void __launch_bounds__(256, 2) attn_kernel(float* __restrict__ outp)
{
    extern __shared__ float sm[];
    float* ks   = sm;                    // [KROWS][128] swizzled k tile
    float* sc   = sm;                    // [TQ][SCW] scores (OVERLAYS ks after use)
    float* qsT  = sm + KROWS * DD;       // [128][QST] q transposed
    float* ssum = qsT + DD * QST;        // [TQ]

    const int tid = threadIdx.x;
    const int blk = blockIdx.x;
    const int b   = blk >> 7;            // / (SS/TQ)
    const int s0  = (blk & 127) * TQ;
    const int lo  = s0 - HALF;

    const float* kg = g_k + (size_t)b * SS * DD;
    const float* vg = g_v + (size_t)b * SS * DD;
    const float* qg = g_q + (size_t)b * SS * DD;

    // ---- load k window (zero-fill out-of-range rows), swizzled ----
    for (int idx = tid; idx < KROWS * 32; idx += 256) {
        int r = idx >> 5, d4 = idx & 31;
        int g = lo + r;
        float4 kv = make_float4(0.f, 0.f, 0.f, 0.f);
        if ((unsigned)g < SS)
            kv = *(const float4*)(kg + (size_t)g * DD + (d4 << 2));
        *(float4*)(ks + swz(r, d4)) = kv;
    }
    // ---- load q transposed: qsT[d][i] ----
    for (int idx = tid; idx < TQ * DD; idx += 256) {
        int i = idx >> 7, d = idx & 127;
        qsT[d * QST + i] = qg[(size_t)(s0 + i) * DD + d];
    }
    __syncthreads();

    // ---- scores: 264 band tiles of 4 queries x 4 key-rows, into REGISTERS ----
    float acc[2][16];
    int i0t[2], r0t[2];
    int ntile = 0;
    #pragma unroll
    for (int p = 0; p < 2; ++p) {
        int t = tid + p * 256;
        if (t < 264) {
            int it = t & 7, rt = t >> 3;
            i0t[p] = it << 2;
            r0t[p] = i0t[p] + (rt << 2);
            score_tile(qsT, ks, i0t[p], r0t[p], acc[p]);
            ntile = p + 1;
        }
    }
    __syncthreads();   // k tile dead; sc may now overlay it

    // ---- zero score padding cells: cols 0..3 and 132..135 per row ----
    {
        int i = tid >> 3, c = tid & 7;           // 32 rows x 8 cells = 256
        sc[i * SCW + ((c < 4) ? c : 128 + c)] = 0.f;
    }
    __syncthreads();

    // ---- write score tiles from registers (each valid cell written once) ----
    const float scale = 0.08838834764831844f;    // 1/sqrt(128)
    for (int p = 0; p < ntile; ++p) {
        int i0 = i0t[p], r0 = r0t[p];
        #pragma unroll
        for (int w = 0; w < 4; ++w) {
            int r = r0 + w;
            bool kvalid = ((unsigned)(lo + r) < SS);
            #pragma unroll
            for (int u = 0; u < 4; ++u) {
                int i = i0 + u;
                int j = r - i;
                if (j >= 0 && j <= 128)
                    sc[i * SCW + 4 + j] = kvalid ? acc[p][u * 4 + w] * scale
                                                 : NEG_INF_F;
            }
        }
    }
    __syncthreads();

    // ---- softmax per row: 8 lanes per row, sub-warp shfl reductions ----
    {
        int i = tid >> 3, jb = tid & 7;
        float* row = sc + i * SCW + 4;
        float m = -INFINITY;
        #pragma unroll
        for (int t = 0; t < 17; ++t) {
            int j = jb + (t << 3);
            if (j < 129) m = fmaxf(m, row[j]);
        }
        m = fmaxf(m, __shfl_xor_sync(0xffffffffu, m, 1, 8));
        m = fmaxf(m, __shfl_xor_sync(0xffffffffu, m, 2, 8));
        m = fmaxf(m, __shfl_xor_sync(0xffffffffu, m, 4, 8));
        float sum = 0.f;
        #pragma unroll
        for (int t = 0; t < 17; ++t) {
            int j = jb + (t << 3);
            if (j < 129) {
                float e = __expf(row[j] - m);
                row[j] = e;
                sum += e;
            }
        }
        sum += __shfl_xor_sync(0xffffffffu, sum, 1, 8);
        sum += __shfl_xor_sync(0xffffffffu, sum, 2, 8);
        sum += __shfl_xor_sync(0xffffffffu, sum, 4, 8);
        if (jb == 0) ssum[i] = sum;
    }
    __syncthreads();

    // ---- output: one warp per 4-query group; v streamed from global (L1 hot) ----
    {
        int it = tid >> 5, dt = tid & 31;        // warp=query group, lane=dim chunk
        int i0 = it << 2;
        float4 o0 = make_float4(0,0,0,0), o1 = o0, o2 = o0, o3 = o0;
        #pragma unroll 4
        for (int rr = 0; rr < 132; ++rr) {
            int r = i0 + rr;
            int g = lo + r;
            int gc = min(max(g, 0), SS - 1);     // clamp; weight is exactly 0 if OOB
            float4 vv = __ldg((const float4*)(vg + (size_t)gc * DD + (dt << 2)));
            const float* srow = sc + i0 * SCW + 4 + (r - i0);
            float p0 = srow[0];                  // j = r - i0        (pads are 0)
            float p1 = srow[SCW - 1];            // j = r - (i0+1)
            float p2 = srow[2 * SCW - 2];
            float p3 = srow[3 * SCW - 3];
            OUT_FMA(o0, p0, vv);
            OUT_FMA(o1, p1, vv);
            OUT_FMA(o2, p2, vv);
            OUT_FMA(o3, p3, vv);
        }
        float inv0 = 1.0f / ssum[i0 + 0];
        float inv1 = 1.0f / ssum[i0 + 1];
        float inv2 = 1.0f / ssum[i0 + 2];
        float inv3 = 1.0f / ssum[i0 + 3];
        float* op = outp + ((size_t)b * SS + s0 + i0) * DD + (dt << 2);
        *(float4*)(op + 0 * DD) = make_float4(o0.x*inv0, o0.y*inv0, o0.z*inv0, o0.w*inv0);
        *(float4*)(op + 1 * DD) = make_float4(o1.x*inv1, o1.y*inv1, o1.z*inv1, o1.w*inv1);
        *(float4*)(op + 2 * DD) = make_float4(o2.x*inv2, o2.y*inv2, o2.z*inv2, o2.w*inv2);
        *(float4*)(op + 3 * DD) = make_float4(o3.x*inv3, o3.y*inv3, o3.z*inv3, o3.w*inv3);
    }
}

extern "C" void kernel_launch(void* const* d_in, const int* in_sizes, int n_in,
                              void* d_out, int out_size)
{
    const float* x  = (const float*)d_in[0];
    const float* Wq = (const float*)d_in[1];
    const float* bq = (const float*)d_in[2];
    const float* Wk = (const float*)d_in[3];
    const float* bk = (const float*)d_in[4];
    const float* Wv = (const float*)d_in[5];
    const float* bv = (const float*)d_in[6];
    float* out = (float*)d_out;

    const int smem_bytes = (KROWS * DD + DD * QST + TQ) * (int)sizeof(float);
    cudaFuncSetAttribute(attn_kernel, cudaFuncAttributeMaxDynamicSharedMemorySize, smem_bytes);

    qkv_kernel<<<BB * SS / 32, 256>>>(x, Wq, bq, Wk, bk, Wv, bv);
    attn_kernel<<<BB * SS / TQ, 256, smem_bytes>>>(out);
}

// round 3
// speedup vs baseline: 1.3973x; 1.2327x over previous
#include <cuda_runtime.h>
#include <math.h>

#define BB 2
#define SS 4096
#define DD 128
#define HALF 64
#define TQ 32
#define KROWS (TQ + 2*HALF)   /* 160 */
#define PW 136                /* per-query prob row: 4 front pad + 129 + 3 back */
#define PWARP (4*PW)          /* 544 floats per warp */
#define NEG_INF_F (-1e30f)

__device__ float g_q[BB*SS*DD];
__device__ float g_k[BB*SS*DD];
__device__ float g_v[BB*SS*DD];

// swizzled float index of 4-float chunk (r, d4) in a [rows][128] tile
__device__ __forceinline__ int swz(int r, int d4) {
    return r * DD + (((d4 ^ r) & 31) << 2);
}

#define QKV_FMA(A, XV, WV) \
    A.x = fmaf(XV, WV.x, A.x); A.y = fmaf(XV, WV.y, A.y); \
    A.z = fmaf(XV, WV.z, A.z); A.w = fmaf(XV, WV.w, A.w);

__global__ void __launch_bounds__(256) qkv_kernel(
    const float* __restrict__ x,
    const float* __restrict__ Wq, const float* __restrict__ bq,
    const float* __restrict__ Wk, const float* __restrict__ bk,
    const float* __restrict__ Wv, const float* __restrict__ bv)
{
    __shared__ float xs[32 * DD];
    const int tid  = threadIdx.x;
    const int row0 = blockIdx.x * 32;

    {   // load 32 x 128 x-tile (float4, coalesced)
        const float4* src = (const float4*)(x + (size_t)row0 * DD);
        float4* dst = (float4*)xs;
        for (int i = tid; i < 32 * DD / 4; i += 256) dst[i] = src[i];
    }
    __syncthreads();

    const int c4 = (tid & 31) << 2;   // output column base (4 cols)
    const int rg = tid >> 5;          // row group 0..7 -> rows rg, rg+8, rg+16, rg+24

    const float* W[3]    = {Wq, Wk, Wv};
    const float* bias[3] = {bq, bk, bv};
    float*       out[3]  = {g_q, g_k, g_v};

    for (int w = 0; w < 3; ++w) {
        float4 b4 = *(const float4*)(bias[w] + c4);
        float4 a0 = b4, a1 = b4, a2 = b4, a3 = b4;
        const float* Wp = W[w] + c4;
        #pragma unroll 4
        for (int k = 0; k < DD; ++k) {
            float4 wv = *(const float4*)(Wp + k * DD);   // L1/L2 resident
            float x0 = xs[(rg     ) * DD + k];           // broadcast LDS
            float x1 = xs[(rg +  8) * DD + k];
            float x2 = xs[(rg + 16) * DD + k];
            float x3 = xs[(rg + 24) * DD + k];
            QKV_FMA(a0, x0, wv);
            QKV_FMA(a1, x1, wv);
            QKV_FMA(a2, x2, wv);
            QKV_FMA(a3, x3, wv);
        }
        float* op = out[w] + (size_t)row0 * DD + c4;
        *(float4*)(op + (size_t)(rg     ) * DD) = a0;
        *(float4*)(op + (size_t)(rg +  8) * DD) = a1;
        *(float4*)(op + (size_t)(rg + 16) * DD) = a2;
        *(float4*)(op + (size_t)(rg + 24) * DD) = a3;
    }
}

#define DOT4A(A, QV, KV) \
    A = fmaf(QV.x, KV.x, A); A = fmaf(QV.y, KV.y, A); \
    A = fmaf(QV.z, KV.z, A); A = fmaf(QV.w, KV.w, A);

#define OUT_FMA(A, P, VV) \
    A.x = fmaf(P, VV.x, A.x); A.y = fmaf(P, VV.y, A.y); \
    A.z = fmaf(P, VV.z, A.z); A.w = fmaf(P, VV.w, A.w);

__global__ void __launch_bounds__(256, 2) attn_kernel(float* __restrict__ outp)
{
    extern __shared__ float sm[];
    float* ks    = sm;                 // [160][128] swizzled k tile (80 KB)
    float* qs    = sm + KROWS * DD;    // [32][128] q row-major  \ union
    float* probs = sm + KROWS * DD;    // [8][544] per-warp probs / (17.4 KB)

    const int tid  = threadIdx.x;
    const int wid  = tid >> 5;
    const int lane = tid & 31;
    const int blk  = blockIdx.x;
    const int b    = blk >> 7;
    const int s0   = (blk & 127) * TQ;
    const int lo   = s0 - HALF;

    const float* kg = g_k + (size_t)b * SS * DD;
    const float* vg = g_v + (size_t)b * SS * DD;
    const float* qg = g_q + (size_t)b * SS * DD;

    // ---- load k window (zero-fill OOB rows), swizzled ----
    for (int idx = tid; idx < KROWS * 32; idx += 256) {
        int r = idx >> 5, d4 = idx & 31;
        int g = lo + r;
        float4 kv = make_float4(0.f, 0.f, 0.f, 0.f);
        if ((unsigned)g < SS)
            kv = *(const float4*)(kg + (size_t)g * DD + (d4 << 2));
        *(float4*)(ks + swz(r, d4)) = kv;
    }
    // ---- load q tile row-major (straight contiguous float4 copy) ----
    {
        const float4* src = (const float4*)(qg + (size_t)s0 * DD);
        float4* dst = (float4*)qs;
        for (int i = tid; i < TQ * 32; i += 256) dst[i] = src[i];
    }
    __syncthreads();

    // ---- scores: warp owns queries iqw..iqw+3; lane owns rows lane+32t ----
    const int iqw = wid << 2;
    float acc[5][4];
    #pragma unroll
    for (int t = 0; t < 5; ++t)
        #pragma unroll
        for (int qi = 0; qi < 4; ++qi) acc[t][qi] = 0.f;

    const float* q0p = qs + (iqw + 0) * DD;
    const float* q1p = qs + (iqw + 1) * DD;
    const float* q2p = qs + (iqw + 2) * DD;
    const float* q3p = qs + (iqw + 3) * DD;

    #pragma unroll 4
    for (int d4 = 0; d4 < 32; ++d4) {
        float4 q0 = *(const float4*)(q0p + (d4 << 2));   // broadcast LDS.128
        float4 q1 = *(const float4*)(q1p + (d4 << 2));
        float4 q2 = *(const float4*)(q2p + (d4 << 2));
        float4 q3 = *(const float4*)(q3p + (d4 << 2));
        #pragma unroll
        for (int t = 0; t < 5; ++t) {
            float4 kv = *(const float4*)(ks + swz(t * 32 + lane, d4));
            DOT4A(acc[t][0], q0, kv);
            DOT4A(acc[t][1], q1, kv);
            DOT4A(acc[t][2], q2, kv);
            DOT4A(acc[t][3], q3, kv);
        }
    }

    // ---- mask + softmax (registers + warp shfl only) ----
    const float scale = 0.08838834764831844f;  // 1/sqrt(128)
    float m[4], wsum[4];
    #pragma unroll
    for (int qi = 0; qi < 4; ++qi) {
        int iq = iqw + qi;
        float mm = -INFINITY;
        #pragma unroll
        for (int t = 0; t < 5; ++t) {
            int r = t * 32 + lane;
            int j = r - iq;
            int g = lo + r;
            bool valid = (j >= 0) && (j <= 128) && ((unsigned)g < SS);
            acc[t][qi] = valid ? acc[t][qi] * scale : NEG_INF_F;
            mm = fmaxf(mm, acc[t][qi]);
        }
        mm = fmaxf(mm, __shfl_xor_sync(0xffffffffu, mm, 1));
        mm = fmaxf(mm, __shfl_xor_sync(0xffffffffu, mm, 2));
        mm = fmaxf(mm, __shfl_xor_sync(0xffffffffu, mm, 4));
        mm = fmaxf(mm, __shfl_xor_sync(0xffffffffu, mm, 8));
        mm = fmaxf(mm, __shfl_xor_sync(0xffffffffu, mm, 16));
        m[qi] = mm;
        float s = 0.f;
        #pragma unroll
        for (int t = 0; t < 5; ++t) {
            float e = __expf(acc[t][qi] - mm);
            acc[t][qi] = e;
            s += e;
        }
        s += __shfl_xor_sync(0xffffffffu, s, 1);
        s += __shfl_xor_sync(0xffffffffu, s, 2);
        s += __shfl_xor_sync(0xffffffffu, s, 4);
        s += __shfl_xor_sync(0xffffffffu, s, 8);
        s += __shfl_xor_sync(0xffffffffu, s, 16);
        wsum[qi] = s;
    }

    __syncthreads();   // everyone done reading qs; probs may overlay it

    // ---- write probs to per-warp strip (zero first; pads must be 0) ----
    float* pw = probs + wid * PWARP;
    for (int i = lane; i < PWARP; i += 32) pw[i] = 0.f;
    __syncwarp();
    #pragma unroll
    for (int qi = 0; qi < 4; ++qi) {
        int iq = iqw + qi;
        #pragma unroll
        for (int t = 0; t < 5; ++t) {
            int j = t * 32 + lane - iq;
            if (j >= -4 && j <= 131)
                pw[qi * PW + 4 + j] = acc[t][qi];
        }
    }
    __syncwarp();

    // ---- output: lane = dim chunk; v streamed from global (L1 hot) ----
    {
        float4 o0 = make_float4(0,0,0,0), o1 = o0, o2 = o0, o3 = o0;
        const float* p0b = pw + 0 * PW + 4;
        const float* p1b = pw + 1 * PW + 3;
        const float* p2b = pw + 2 * PW + 2;
        const float* p3b = pw + 3 * PW + 1;
        #pragma unroll 4
        for (int rr = 0; rr < 132; ++rr) {
            int g = lo + iqw + rr;
            int gc = min(max(g, 0), SS - 1);   // clamp; weight exactly 0 if OOB
            float4 vv = __ldg((const float4*)(vg + (size_t)gc * DD + (lane << 2)));
            float p0 = p0b[rr];                // broadcast reads, pads are 0
            float p1 = p1b[rr];
            float p2 = p2b[rr];
            float p3 = p3b[rr];
            OUT_FMA(o0, p0, vv);
            OUT_FMA(o1, p1, vv);
            OUT_FMA(o2, p2, vv);
            OUT_FMA(o3, p3, vv);
        }
        float inv0 = 1.0f / wsum[0];
        float inv1 = 1.0f / wsum[1];
        float inv2 = 1.0f / wsum[2];
        float inv3 = 1.0f / wsum[3];
        float* op = outp + ((size_t)b * SS + s0 + iqw) * DD + (lane << 2);
        *(float4*)(op + 0 * DD) = make_float4(o0.x*inv0, o0.y*inv0, o0.z*inv0, o0.w*inv0);
        *(float4*)(op + 1 * DD) = make_float4(o1.x*inv1, o1.y*inv1, o1.z*inv1, o1.w*inv1);
        *(float4*)(op + 2 * DD) = make_float4(o2.x*inv2, o2.y*inv2, o2.z*inv2, o2.w*inv2);
        *(float4*)(op + 3 * DD) = make_float4(o3.x*inv3, o3.y*inv3, o3.z*inv3, o3.w*inv3);
    }
}

extern "C" void kernel_launch(void* const* d_in, const int* in_sizes, int n_in,
                              void* d_out, int out_size)
{
    const float* x  = (const float*)d_in[0];
    const float* Wq = (const float*)d_in[1];
    const float* bq = (const float*)d_in[2];
    const float* Wk = (const float*)d_in[3];
    const float* bk = (const float*)d_in[4];
    const float* Wv = (const float*)d_in[5];
    const float* bv = (const float*)d_in[6];
    float* out = (float*)d_out;

    const int union_floats = (8 * PWARP > TQ * DD) ? 8 * PWARP : TQ * DD;
    const int smem_bytes = (KROWS * DD + union_floats) * (int)sizeof(float);
    cudaFuncSetAttribute(attn_kernel, cudaFuncAttributeMaxDynamicSharedMemorySize, smem_bytes);

    qkv_kernel<<<BB * SS / 32, 256>>>(x, Wq, bq, Wk, bk, Wv, bv);
    attn_kernel<<<BB * SS / TQ, 256, smem_bytes>>>(out);
}